// round 12
// baseline (speedup 1.0000x reference)
#include <cuda_runtime.h>
#include <cstdint>

#define NC  5
#define TPB 256
#define MAXROWS 2097152

__device__ __forceinline__ float fast_ex2(float x) {
    float y; asm("ex2.approx.f32 %0, %1;" : "=f"(y) : "f"(x)); return y;
}
__device__ __forceinline__ float fast_lg2(float x) {
    float y; asm("lg2.approx.f32 %0, %1;" : "=f"(y) : "f"(x)); return y;
}
__device__ __forceinline__ float fast_rcp(float x) {
    float y; asm("rcp.approx.f32 %0, %1;" : "=f"(y) : "f"(x)); return y;
}
__device__ __forceinline__ float fast_rsq(float x) {
    float y; asm("rsqrt.approx.f32 %0, %1;" : "=f"(y) : "f"(x)); return y;
}

// h(t) = t*mu(t) - log2 Z(t) + C2 (log2 domain), C2=(ln5-eps)/ln2, increasing.
// p(t) = softmax(t*ln q) is invariant to rescaling q, so normalized rows work.
#define C2CONST 2.1776498f     // (ln5 - 0.1)/ln2
#define LN2SQ   0.48045302f    // ln2^2
#define LN2CU   0.33302465f    // ln2^3
#define RLN2    1.44269504f    // 1/ln2
#define SQ2EPS  0.44721360f    // sqrt(2*eps)

__device__ int g_count;
__device__ int g_queue[MAXROWS];   // 8 MB static scratch (allowed)

__device__ __forceinline__ float solve_row(const float L[NC]) {
    float s1 = 0.f, s2 = 0.f, s3 = 0.f;
    #pragma unroll
    for (int j = 0; j < NC; j++) {
        float lj = L[j];
        s1 += lj; s2 = fmaf(lj, lj, s2); s3 = fmaf(lj * lj, lj, s3);
    }
    float m   = s1 * 0.2f;
    float e2  = s2 * 0.2f;
    float V   = fmaxf(LN2SQ * (e2 - m * m), 1e-9f);
    float m3  = LN2CU * fmaf(s3, 0.2f, fmaf(-3.f * m, e2, 2.f * m * m * m));
    float tl  = SQ2EPS * fast_rsq(V);
    float den = fmaxf(fmaf(0.6666667f * m3, tl, V), 1e-9f);
    float tc  = fminf(0.95f, fmaxf(SQ2EPS * fast_rsq(den), 1e-4f));

    float lo = 0.f, hi = 1.f;
    #pragma unroll
    for (int it = 0; it < 3; ++it) {
        float S = 0.f, A = 0.f, B = 0.f;
        #pragma unroll
        for (int j = 0; j < NC; j++) {
            float e  = fast_ex2(tc * L[j]);
            float el = e * L[j];
            S += e; A = fmaf(e, L[j], A); B = fmaf(el, L[j], B);
        }
        float r  = fast_rcp(S);
        float mu = A * r;
        float v  = fmaf(B, r, -(mu * mu));
        float h  = fmaf(tc, mu, C2CONST - fast_lg2(S));
        float hp = tc * v;
        bool pos = (h > 0.f);
        hi = pos ? tc : hi;
        lo = pos ? lo : tc;
        float tn = fmaf(-h * RLN2, fast_rcp(hp), tc);
        bool ok = (tn > lo) && (tn < hi);   // false also on NaN
        tc = ok ? tn : 0.5f * (lo + hi);
    }
    return tc;
}

__global__ void zero_count() { g_count = 0; }

// ---- Pass 1: lean common path (NO solver), vec4 I/O, queue infeasible rows ----
__global__ void __launch_bounds__(TPB) pass1_vec4(
    const float4* __restrict__ x4,
    const float*  __restrict__ W,
    const float*  __restrict__ b,
    float4* __restrict__ o4)
{
    __shared__ float sW[NC * NC];
    __shared__ float sb[NC];
    if (threadIdx.x < NC * NC) sW[threadIdx.x] = W[threadIdx.x];
    if (threadIdx.x < NC)      sb[threadIdx.x] = b[threadIdx.x];
    __syncthreads();

    size_t g = (size_t)blockIdx.x * TPB + threadIdx.x;
    const float4* xin = x4 + g * 5;

    float a[20];
    #pragma unroll
    for (int i = 0; i < 5; i++) {
        float4 v = xin[i];
        a[4*i+0] = v.x; a[4*i+1] = v.y; a[4*i+2] = v.z; a[4*i+3] = v.w;
    }

    int bad = 0;   // bitmask of infeasible local rows
    #pragma unroll
    for (int r = 0; r < 4; r++) {
        float q[NC];
        float s = 0.f, A = 0.f;
        #pragma unroll
        for (int j = 0; j < NC; j++) {
            float qq = sb[j];
            #pragma unroll
            for (int k = 0; k < NC; k++) qq = fmaf(a[r*NC + k], sW[j*NC + k], qq);
            q[j] = qq;
            s += qq;
            A = fmaf(qq, fast_lg2(qq), A);     // lg2 transient
        }
        float ir = fast_rcp(s);
        float h1 = A * ir - fast_lg2(s) + C2CONST;
        if (h1 > 0.f) bad |= (1 << r);
        #pragma unroll
        for (int j = 0; j < NC; j++) a[r*NC + j] = q[j] * ir;  // p = q/sum(q)
    }

    // Write result for ALL rows (exact for feasible; normalized base for pass 2).
    float4* oo = o4 + g * 5;
    #pragma unroll
    for (int i = 0; i < 5; i++)
        oo[i] = make_float4(a[4*i+0], a[4*i+1], a[4*i+2], a[4*i+3]);

    // Warp-aggregated queue push of infeasible row indices.
    int mycnt = __popc(bad);
    unsigned pmask = __ballot_sync(0xffffffffu, mycnt > 0);
    if (pmask) {
        // prefix sum of counts within warp
        int lane = threadIdx.x & 31;
        int pre = mycnt;
        #pragma unroll
        for (int off = 1; off < 32; off <<= 1) {
            int v = __shfl_up_sync(0xffffffffu, pre, off);
            if (lane >= off) pre += v;
        }
        int total = __shfl_sync(0xffffffffu, pre, 31);
        int base = 0;
        if (lane == 31) base = atomicAdd(&g_count, total);
        base = __shfl_sync(0xffffffffu, base, 31);
        int pos = base + pre - mycnt;
        int bb = bad;
        while (bb) {
            int r = __ffs(bb) - 1;
            bb &= bb - 1;
            g_queue[pos++] = (int)(g * 4 + r);
        }
    }
}

// ---- Pass 2: dense solve over queued rows, reading normalized q from out ----
__global__ void __launch_bounds__(TPB) pass2_fix(float* __restrict__ out)
{
    int count = g_count;
    for (int i = blockIdx.x * blockDim.x + threadIdx.x;
         i < count;
         i += gridDim.x * blockDim.x)
    {
        int row = g_queue[i];
        float* po = out + (size_t)row * NC;
        float L[NC];
        #pragma unroll
        for (int j = 0; j < NC; j++) L[j] = fast_lg2(po[j]);   // softmax scale-inv
        float t = solve_row(L);
        float e[NC], S = 0.f;
        #pragma unroll
        for (int j = 0; j < NC; j++) { e[j] = fast_ex2(t * L[j]); S += e[j]; }
        float r = fast_rcp(S);
        #pragma unroll
        for (int j = 0; j < NC; j++) po[j] = e[j] * r;
    }
}

// ---- Scalar fallback (any alignment / row count): self-contained ----
__global__ void __launch_bounds__(TPB) kl_proj_scalar(
    const float* __restrict__ x,
    const float* __restrict__ W,
    const float* __restrict__ b,
    float* __restrict__ out,
    int n)
{
    __shared__ float sW[NC * NC];
    __shared__ float sb[NC];
    if (threadIdx.x < NC * NC) sW[threadIdx.x] = W[threadIdx.x];
    if (threadIdx.x < NC)      sb[threadIdx.x] = b[threadIdx.x];
    __syncthreads();

    int row = blockIdx.x * blockDim.x + threadIdx.x;
    if (row >= n) return;

    float xv[NC];
    #pragma unroll
    for (int k = 0; k < NC; k++) xv[k] = x[row * NC + k];

    float q[NC];
    float s = 0.f, A = 0.f;
    #pragma unroll
    for (int j = 0; j < NC; j++) {
        float qq = sb[j];
        #pragma unroll
        for (int k = 0; k < NC; k++) qq = fmaf(xv[k], sW[j*NC + k], qq);
        q[j] = qq; s += qq;
        A = fmaf(qq, fast_lg2(qq), A);
    }
    float ir = fast_rcp(s);
    float h1 = A * ir - fast_lg2(s) + C2CONST;
    if (h1 > 0.f) {
        float L[NC];
        #pragma unroll
        for (int j = 0; j < NC; j++) L[j] = fast_lg2(q[j]);
        float t = solve_row(L);
        float S = 0.f;
        #pragma unroll
        for (int j = 0; j < NC; j++) { q[j] = fast_ex2(t * L[j]); S += q[j]; }
        ir = fast_rcp(S);
    }
    #pragma unroll
    for (int j = 0; j < NC; j++) out[row * NC + j] = q[j] * ir;
}

extern "C" void kernel_launch(void* const* d_in, const int* in_sizes, int n_in,
                              void* d_out, int out_size) {
    const float* x = (const float*)d_in[0];
    const float* W = (const float*)d_in[1];
    const float* b = (const float*)d_in[2];
    float* out = (float*)d_out;
    int n = in_sizes[0] / NC;

    bool aligned = ((((uintptr_t)x) | ((uintptr_t)out)) & 15u) == 0
                   && (n % (TPB * 4)) == 0 && n <= MAXROWS;
    if (aligned) {
        zero_count<<<1, 1>>>();
        pass1_vec4<<<n / (TPB * 4), TPB>>>((const float4*)x, W, b, (float4*)out);
        pass2_fix<<<1024, TPB>>>(out);
    } else {
        kl_proj_scalar<<<(n + TPB - 1) / TPB, TPB>>>(x, W, b, out, n);
    }
}